// round 3
// baseline (speedup 1.0000x reference)
#include <cuda_runtime.h>
#include <cstdint>

// ---------------------------------------------------------------------------
// SLAYER SNN pipeline, t-major intermediates:
//   K0 : pool4 input (n,c,256,256,t) -> p0 (n,t,2,64,64)     [DRAM-bound floor]
//   K1a: conv1 7x7 pad3 (2->4) per (n,t) slab -> u1          [f32x2, LDS.128]
//   K1b: spike scan over t, pure recurrence -> s1 bytes
//   K2a: dp4a pool of s1 + conv2 (4->8), 4px/thread f32x2 -> u2
//   K2b: spike scan over t -> s2 bytes
//   K3 : dp4a pool + einsum wl -> out (n,2,t)
// ---------------------------------------------------------------------------

#define NB 4
#define TT 100

__device__ float g_p0[NB*TT*2*64*64];          // 3,276,800 floats
__device__ float g_u1[NB*TT*4*64*64];          // 6,553,600 floats
__device__ unsigned char g_s1[NB*TT*4*64*64];  // 6,553,600 bytes
__device__ float g_u2[NB*TT*8*16*16];          //   819,200 floats
__device__ unsigned char g_s2[NB*TT*8*16*16];  //   819,200 bytes

__constant__ float c_w0[4*2*7*7];    // 392
__constant__ float c_w1[8*4*7*7];    // 1568
__constant__ float c_wl[2*8*4*4];    // 256

// ---- packed f32x2 helpers (sm_100+) ----
__device__ __forceinline__ unsigned long long pack2(float lo, float hi) {
    unsigned long long r;
    asm("mov.b64 %0, {%1, %2};" : "=l"(r) : "f"(lo), "f"(hi));
    return r;
}
__device__ __forceinline__ void unpack2(unsigned long long v, float& lo, float& hi) {
    asm("mov.b64 {%0, %1}, %2;" : "=f"(lo), "=f"(hi) : "l"(v));
}
__device__ __forceinline__ unsigned long long fma2(unsigned long long a,
                                                   unsigned long long b,
                                                   unsigned long long c) {
    unsigned long long d;
    asm("fma.rn.f32x2 %0, %1, %2, %3;" : "=l"(d) : "l"(a), "l"(b), "l"(c));
    return d;
}
__device__ __forceinline__ int dp4a_sum(unsigned int u, int acc) {
    int r;
    asm("dp4a.u32.u32 %0, %1, %2, %3;" : "=r"(r)
        : "r"(u), "r"(0x01010101u), "r"(acc));
    return r;
}

// ---------------------------------------------------------------------------
// K0: 4x4 average pool of raw input with layout transpose to t-major.
// 512 blocks = (n,c,H64), 256 threads. Reads 210MB coalesced (float4 over t).
// ---------------------------------------------------------------------------
__global__ void __launch_bounds__(256) k0_pool(const float* __restrict__ in) {
    const int b = blockIdx.x;
    const int n = b >> 7, c = (b >> 6) & 1, H = b & 63;
    __shared__ float sm[TT][65];   // [t][W]

    const float* base = in + (size_t)((n*2 + c)*256 + H*4) * 25600;

    for (int idx = threadIdx.x; idx < 1600; idx += 256) {
        int W  = idx / 25;
        int tq = idx - W*25;           // t-quad 0..24
        const float4* p = (const float4*)(base + (size_t)(W*4)*100 + tq*4);
        float4 s = make_float4(0.f, 0.f, 0.f, 0.f);
#pragma unroll
        for (int dy = 0; dy < 4; dy++)
#pragma unroll
            for (int dx = 0; dx < 4; dx++) {
                float4 v = p[dy*6400 + dx*25];
                s.x += v.x; s.y += v.y; s.z += v.z; s.w += v.w;
            }
        int t = tq*4;
        sm[t+0][W] = s.x*0.0625f; sm[t+1][W] = s.y*0.0625f;
        sm[t+2][W] = s.z*0.0625f; sm[t+3][W] = s.w*0.0625f;
    }
    __syncthreads();
    const size_t ob = ((size_t)(n*TT)*2 + c)*4096 + H*64;
    for (int idx = threadIdx.x; idx < 6400; idx += 256) {
        int t = idx >> 6, W = idx & 63;
        g_p0[ob + (size_t)t*8192 + W] = sm[t][W];
    }
}

// ---------------------------------------------------------------------------
// K1a: conv1 2->4ch 7x7 pad3 on 64x64, one (n,t) slab per block, 256 threads.
// f32x2: 2 output pixels per FMA; inputs via aligned LDS.128 (stride 72).
// Weights warp-uniform from constant (LDCU path).
// ---------------------------------------------------------------------------
__global__ void __launch_bounds__(256, 2) k1a_conv1() {
    const int b = blockIdx.x;              // n*100 + t
    __shared__ float si[2*70*72];          // zero-padded input, stride 72

    for (int i = threadIdx.x; i < 2*70*72; i += 256) si[i] = 0.f;
    __syncthreads();
    const float* slab = g_p0 + (size_t)b * 8192;
    for (int i = threadIdx.x; i < 8192; i += 256) {
        int ci = i >> 12, h = (i >> 6) & 63, w = i & 63;
        si[ci*5040 + (h+3)*72 + (w+3)] = slab[i];
    }
    __syncthreads();

    float* out = g_u1 + (size_t)b * 16384;

#pragma unroll 1
    for (int rep = 0; rep < 2; rep++) {
        const int pos = threadIdx.x + (rep << 8);   // 0..511
        const int h  = pos >> 3;
        const int ws = (pos & 7) << 3;              // 8-pixel segment start
        unsigned long long acc[4][4];
#pragma unroll
        for (int o = 0; o < 4; o++)
#pragma unroll
            for (int k = 0; k < 4; k++) acc[o][k] = 0ull;

#pragma unroll 1
        for (int ci = 0; ci < 2; ci++) {
#pragma unroll 1
            for (int dy = 0; dy < 7; dy++) {
                const float* r = si + ci*5040 + (h+dy)*72 + ws;  // 16B-aligned
                float v[16];
#pragma unroll
                for (int q = 0; q < 4; q++) {
                    float4 t4 = ((const float4*)r)[q];
                    v[4*q+0] = t4.x; v[4*q+1] = t4.y;
                    v[4*q+2] = t4.z; v[4*q+3] = t4.w;
                }
                unsigned long long pe[7], po[6];
#pragma unroll
                for (int j = 0; j < 7; j++) pe[j] = pack2(v[2*j],   v[2*j+1]);
#pragma unroll
                for (int j = 0; j < 6; j++) po[j] = pack2(v[2*j+1], v[2*j+2]);
                const float* wrow = c_w0 + (ci*7 + dy)*7;   // + o*98 + dx
#pragma unroll
                for (int dx = 0; dx < 7; dx++) {
#pragma unroll
                    for (int o = 0; o < 4; o++) {
                        float wv = wrow[o*98 + dx];
                        unsigned long long wp = pack2(wv, wv);
#pragma unroll
                        for (int k = 0; k < 4; k++) {
                            unsigned long long inp =
                                (dx & 1) ? po[(dx >> 1) + k] : pe[(dx >> 1) + k];
                            acc[o][k] = fma2(inp, wp, acc[o][k]);
                        }
                    }
                }
            }
        }
#pragma unroll
        for (int o = 0; o < 4; o++) {
            float res[8];
#pragma unroll
            for (int k = 0; k < 4; k++) unpack2(acc[o][k], res[2*k], res[2*k+1]);
            float4* dst = (float4*)(out + o*4096 + h*64 + ws);
            dst[0] = make_float4(res[0], res[1], res[2], res[3]);
            dst[1] = make_float4(res[4], res[5], res[6], res[7]);
        }
    }
}

// ---------------------------------------------------------------------------
// K1b: spike scan layer 1 — pure per-thread recurrence, no barriers.
// 16384 threads (256 blocks x 64, full SM coverage), thread owns 4 adjacent
// w-locations (float4 in, uchar4 out), depth-4 temporal prefetch.
// ---------------------------------------------------------------------------
__global__ void __launch_bounds__(64) k1b_scan1() {
    const int g = blockIdx.x*64 + threadIdx.x;      // 0..16383
    const int n = g >> 12, r = g & 4095;            // r: (c,h,wq) 4*64*16
    const float4* ub = (const float4*)g_u1 + (size_t)(n*TT)*4096 + r;  // +t*4096
    uchar4* sp = (uchar4*)g_s1 + (size_t)(n*TT)*4096 + r;              // +t*4096

    float m0 = 0.f, m1 = 0.f, m2 = 0.f, m3 = 0.f;
    float4 buf[4];
#pragma unroll
    for (int i = 0; i < 4; i++) buf[i] = ub[(size_t)i*4096];

#pragma unroll 1
    for (int tg = 0; tg < 25; tg++) {
        float4 c0 = buf[0], c1 = buf[1], c2 = buf[2], c3 = buf[3];
        if (tg < 24) {
#pragma unroll
            for (int i = 0; i < 4; i++)
                buf[i] = ub[(size_t)(tg*4 + 4 + i)*4096];
        }
#pragma unroll
        for (int i = 0; i < 4; i++) {
            float4 c = (i == 0) ? c0 : (i == 1) ? c1 : (i == 2) ? c2 : c3;
            m0 += c.x; float s0 = (m0 >= 1.f) ? 1.f : 0.f; m0 -= s0;
            m1 += c.y; float s1 = (m1 >= 1.f) ? 1.f : 0.f; m1 -= s1;
            m2 += c.z; float s2 = (m2 >= 1.f) ? 1.f : 0.f; m2 -= s2;
            m3 += c.w; float s3 = (m3 >= 1.f) ? 1.f : 0.f; m3 -= s3;
            sp[(size_t)(tg*4 + i)*4096] =
                make_uchar4((unsigned char)s0, (unsigned char)s1,
                            (unsigned char)s2, (unsigned char)s3);
        }
    }
}

// ---------------------------------------------------------------------------
// K2a: dp4a 4x4 pool of s1 bytes + conv2 4->8ch 7x7 pad3 on 16x16.
// 2 slabs per block (grid 200, 128 threads). Thread = (h, w-quad): 4 output
// pixels x 8 oc, as two f32x2 pixel-pairs per oc. Weight dup-packs in smem
// (broadcast LDS.64) amortized over 4 pixels; inputs via 3 aligned LDS.128.
// ---------------------------------------------------------------------------
__global__ void __launch_bounds__(128) k2a_conv2() {
    const int bp = blockIdx.x;             // 0..199
    __shared__ float pp[2][4*22*24];       // per-slab padded pooled input
    __shared__ unsigned long long wdd[8*196];  // (w,w) dup packs

    const int tid = threadIdx.x;
    const int sel = tid >> 6, l = tid & 63;
    const int slab = bp*2 + sel;           // n*100 + t

    for (int i = tid; i < 1568; i += 128) {
        float wv = c_w1[i];                // i = o*196 + (ci*49+dy*7+dx)
        wdd[i] = pack2(wv, wv);
    }
    for (int i = l; i < 2112; i += 64) pp[sel][i] = 0.f;
    __syncthreads();

    // pool: 1024 pooled values per slab, dp4a over 4 rows of 4 spike bytes
    const unsigned char* sslab = g_s1 + (size_t)slab * 16384;
    for (int i = l; i < 1024; i += 64) {
        int ci = i >> 8, ph = (i >> 4) & 15, pw = i & 15;
        const unsigned int* srow =
            (const unsigned int*)(sslab + ci*4096 + ph*256) + pw;
        int s = 0;
#pragma unroll
        for (int rr = 0; rr < 4; rr++) s = dp4a_sum(srow[rr*16], s);
        pp[sel][ci*528 + (ph+3)*24 + (pw+3)] = (float)s * 0.0625f;
    }
    __syncthreads();

    const int h = l >> 2, w0 = (l & 3) << 2;
    unsigned long long acc[8][2];
#pragma unroll
    for (int o = 0; o < 8; o++) { acc[o][0] = 0ull; acc[o][1] = 0ull; }

#pragma unroll 1
    for (int ci = 0; ci < 4; ci++) {
#pragma unroll 1
        for (int dy = 0; dy < 7; dy++) {
            const float* row = &pp[sel][ci*528 + (h+dy)*24 + w0];
            float v[12];
#pragma unroll
            for (int q = 0; q < 3; q++) {
                float4 t4 = ((const float4*)row)[q];
                v[4*q+0] = t4.x; v[4*q+1] = t4.y;
                v[4*q+2] = t4.z; v[4*q+3] = t4.w;
            }
            unsigned long long pa[7], pb[7];
#pragma unroll
            for (int dx = 0; dx < 7; dx++) {
                pa[dx] = pack2(v[dx],     v[dx + 1]);
                pb[dx] = pack2(v[dx + 2], v[dx + 3]);
            }
            const unsigned long long* wr = wdd + ci*49 + dy*7;
#pragma unroll
            for (int dx = 0; dx < 7; dx++) {
#pragma unroll
                for (int o = 0; o < 8; o++) {
                    unsigned long long wp = wr[o*196 + dx];  // broadcast
                    acc[o][0] = fma2(pa[dx], wp, acc[o][0]);
                    acc[o][1] = fma2(pb[dx], wp, acc[o][1]);
                }
            }
        }
    }
    float* out = g_u2 + (size_t)slab * 2048;
#pragma unroll
    for (int o = 0; o < 8; o++) {
        float r0, r1, r2, r3;
        unpack2(acc[o][0], r0, r1);
        unpack2(acc[o][1], r2, r3);
        *(float4*)(out + o*256 + h*16 + w0) = make_float4(r0, r1, r2, r3);
    }
}

// ---------------------------------------------------------------------------
// K2b: spike scan layer 2 -> s2 bytes. 8192 threads (256 blocks x 32).
// ---------------------------------------------------------------------------
__global__ void __launch_bounds__(32) k2b_scan2() {
    const int g = blockIdx.x*32 + threadIdx.x;      // 0..8191
    const int n = g >> 11, r = g & 2047;
    const float* ub = g_u2 + (size_t)(n*TT)*2048 + r;     // +t*2048
    unsigned char* sp = g_s2 + (size_t)(n*TT)*2048 + r;

    float m = 0.f;
    float buf[4];
#pragma unroll
    for (int i = 0; i < 4; i++) buf[i] = ub[(size_t)i*2048];

#pragma unroll 1
    for (int tg = 0; tg < 25; tg++) {
        float c0 = buf[0], c1 = buf[1], c2 = buf[2], c3 = buf[3];
        if (tg < 24) {
#pragma unroll
            for (int i = 0; i < 4; i++)
                buf[i] = ub[(size_t)(tg*4 + 4 + i)*2048];
        }
        float cc[4] = {c0, c1, c2, c3};
#pragma unroll
        for (int i = 0; i < 4; i++) {
            m += cc[i];
            float s = (m >= 1.f) ? 1.f : 0.f;
            m -= s;
            sp[(size_t)(tg*4 + i)*2048] = (unsigned char)s;
        }
    }
}

// ---------------------------------------------------------------------------
// K3: dp4a pool of s2 + einsum with wl -> out (n,2,t). 400 blocks x 64 thr.
// ---------------------------------------------------------------------------
__global__ void __launch_bounds__(64) k3_out(float* __restrict__ out) {
    const int b = blockIdx.x;
    const int n = b / 100, t = b - n*100;
    const unsigned int* slab = (const unsigned int*)(g_s2 + (size_t)b * 2048);
    const int tid = threadIdx.x;
    float a0 = 0.f, a1 = 0.f;
    for (int i = tid; i < 512; i += 64) {
        int cnt = dp4a_sum(slab[i], 0);
        int cc = i >> 6;
        int hh = (i >> 2) & 15;
        int wq = i & 3;
        int wi = cc*16 + (hh >> 2)*4 + wq;
        float f = (float)cnt;
        a0 += f * c_wl[wi];
        a1 += f * c_wl[128 + wi];
    }
    __shared__ float r0[64], r1[64];
    r0[tid] = a0; r1[tid] = a1;
    __syncthreads();
    if (tid < 32) {
        float v0 = r0[tid] + r0[tid+32];
        float v1 = r1[tid] + r1[tid+32];
#pragma unroll
        for (int off = 16; off > 0; off >>= 1) {
            v0 += __shfl_down_sync(0xffffffffu, v0, off);
            v1 += __shfl_down_sync(0xffffffffu, v1, off);
        }
        if (tid == 0) {
            out[(n*2 + 0)*100 + t] = v0 * 0.0625f;
            out[(n*2 + 1)*100 + t] = v1 * 0.0625f;
        }
    }
}

// ---------------------------------------------------------------------------
extern "C" void kernel_launch(void* const* d_in, const int* in_sizes, int n_in,
                              void* d_out, int out_size) {
    (void)in_sizes; (void)n_in; (void)out_size;
    const float* data = (const float*)d_in[0];

    cudaMemcpyToSymbolAsync(c_w0, d_in[1], sizeof(float)*392,  0,
                            cudaMemcpyDeviceToDevice, 0);
    cudaMemcpyToSymbolAsync(c_w1, d_in[2], sizeof(float)*1568, 0,
                            cudaMemcpyDeviceToDevice, 0);
    cudaMemcpyToSymbolAsync(c_wl, d_in[3], sizeof(float)*256,  0,
                            cudaMemcpyDeviceToDevice, 0);

    k0_pool  <<<512, 256>>>(data);
    k1a_conv1<<<400, 256>>>();
    k1b_scan1<<<256,  64>>>();
    k2a_conv2<<<200, 128>>>();
    k2b_scan2<<<256,  32>>>();
    k3_out   <<<400,  64>>>((float*)d_out);
}

// round 4
// speedup vs baseline: 1.0146x; 1.0146x over previous
#include <cuda_runtime.h>
#include <cstdint>

// ---------------------------------------------------------------------------
// SLAYER SNN pipeline, t-major intermediates:
//   K0 : pool4 input (n,c,256,256,t) -> p0 (n,t,2,64,64)     [DRAM-bound floor]
//   K1a: conv1 7x7 pad3 (2->4) per (n,t) slab -> u1          [f32x2, smem wts]
//   K1b: spike scan over t, pure recurrence -> s1 bytes
//   K2a: dp4a pool of s1 + conv2 (4->8), 4px x 4oc/thread -> u2
//   K2b: spike scan over t -> s2 bytes
//   K3 : dp4a pool + einsum wl -> out (n,2,t)
// ---------------------------------------------------------------------------

#define NB 4
#define TT 100

__device__ float g_p0[NB*TT*2*64*64];          // 3,276,800 floats
__device__ float g_u1[NB*TT*4*64*64];          // 6,553,600 floats
__device__ unsigned char g_s1[NB*TT*4*64*64];  // 6,553,600 bytes
__device__ float g_u2[NB*TT*8*16*16];          //   819,200 floats
__device__ unsigned char g_s2[NB*TT*8*16*16];  //   819,200 bytes

__constant__ float c_w0[4*2*7*7];    // 392
__constant__ float c_w1[8*4*7*7];    // 1568
__constant__ float c_wl[2*8*4*4];    // 256

// ---- packed f32x2 helpers (sm_100+) ----
__device__ __forceinline__ unsigned long long pack2(float lo, float hi) {
    unsigned long long r;
    asm("mov.b64 %0, {%1, %2};" : "=l"(r) : "f"(lo), "f"(hi));
    return r;
}
__device__ __forceinline__ void unpack2(unsigned long long v, float& lo, float& hi) {
    asm("mov.b64 {%0, %1}, %2;" : "=f"(lo), "=f"(hi) : "l"(v));
}
__device__ __forceinline__ unsigned long long fma2(unsigned long long a,
                                                   unsigned long long b,
                                                   unsigned long long c) {
    unsigned long long d;
    asm("fma.rn.f32x2 %0, %1, %2, %3;" : "=l"(d) : "l"(a), "l"(b), "l"(c));
    return d;
}
__device__ __forceinline__ int dp4a_sum(unsigned int u, int acc) {
    int r;
    asm("dp4a.u32.u32 %0, %1, %2, %3;" : "=r"(r)
        : "r"(u), "r"(0x01010101u), "r"(acc));
    return r;
}

// ---------------------------------------------------------------------------
// K0: 4x4 average pool of raw input with layout transpose to t-major.
// 512 blocks = (n,c,H64), 256 threads. Reads 210MB coalesced (float4 over t).
// ---------------------------------------------------------------------------
__global__ void __launch_bounds__(256) k0_pool(const float* __restrict__ in) {
    const int b = blockIdx.x;
    const int n = b >> 7, c = (b >> 6) & 1, H = b & 63;
    __shared__ float sm[TT][65];   // [t][W]

    const float* base = in + (size_t)((n*2 + c)*256 + H*4) * 25600;

    for (int idx = threadIdx.x; idx < 1600; idx += 256) {
        int W  = idx / 25;
        int tq = idx - W*25;           // t-quad 0..24
        const float4* p = (const float4*)(base + (size_t)(W*4)*100 + tq*4);
        float4 s = make_float4(0.f, 0.f, 0.f, 0.f);
#pragma unroll
        for (int dy = 0; dy < 4; dy++)
#pragma unroll
            for (int dx = 0; dx < 4; dx++) {
                float4 v = p[dy*6400 + dx*25];
                s.x += v.x; s.y += v.y; s.z += v.z; s.w += v.w;
            }
        int t = tq*4;
        sm[t+0][W] = s.x*0.0625f; sm[t+1][W] = s.y*0.0625f;
        sm[t+2][W] = s.z*0.0625f; sm[t+3][W] = s.w*0.0625f;
    }
    __syncthreads();
    const size_t ob = ((size_t)(n*TT)*2 + c)*4096 + H*64;
    for (int idx = threadIdx.x; idx < 6400; idx += 256) {
        int t = idx >> 6, W = idx & 63;
        g_p0[ob + (size_t)t*8192 + W] = sm[t][W];
    }
}

// ---------------------------------------------------------------------------
// K1a: conv1 2->4ch 7x7 pad3 on 64x64, one (n,t) slab per block, 256 threads.
// f32x2: 2 output pixels per FMA; inputs via aligned LDS.128 (stride 72);
// weights as (w,w) dup-packs in smem (broadcast LDS.64) -- avoids the
// half-rate constant port that bound the previous version.
// ---------------------------------------------------------------------------
__global__ void __launch_bounds__(256, 2) k1a_conv1() {
    const int b = blockIdx.x;              // n*100 + t
    __shared__ float si[2*70*72];          // zero-padded input, stride 72
    __shared__ unsigned long long wdd0[392];  // (w,w) dup packs of c_w0

    for (int i = threadIdx.x; i < 392; i += 256) {
        float wv = c_w0[i];
        wdd0[i] = pack2(wv, wv);
    }
    for (int i = threadIdx.x; i < 2*70*72; i += 256) si[i] = 0.f;
    __syncthreads();
    const float* slab = g_p0 + (size_t)b * 8192;
    for (int i = threadIdx.x; i < 8192; i += 256) {
        int ci = i >> 12, h = (i >> 6) & 63, w = i & 63;
        si[ci*5040 + (h+3)*72 + (w+3)] = slab[i];
    }
    __syncthreads();

    float* out = g_u1 + (size_t)b * 16384;

#pragma unroll 1
    for (int rep = 0; rep < 2; rep++) {
        const int pos = threadIdx.x + (rep << 8);   // 0..511
        const int h  = pos >> 3;
        const int ws = (pos & 7) << 3;              // 8-pixel segment start
        unsigned long long acc[4][4];
#pragma unroll
        for (int o = 0; o < 4; o++)
#pragma unroll
            for (int k = 0; k < 4; k++) acc[o][k] = 0ull;

#pragma unroll 1
        for (int ci = 0; ci < 2; ci++) {
#pragma unroll 1
            for (int dy = 0; dy < 7; dy++) {
                const float* r = si + ci*5040 + (h+dy)*72 + ws;  // 16B-aligned
                float v[16];
#pragma unroll
                for (int q = 0; q < 4; q++) {
                    float4 t4 = ((const float4*)r)[q];
                    v[4*q+0] = t4.x; v[4*q+1] = t4.y;
                    v[4*q+2] = t4.z; v[4*q+3] = t4.w;
                }
                unsigned long long pe[7], po[6];
#pragma unroll
                for (int j = 0; j < 7; j++) pe[j] = pack2(v[2*j],   v[2*j+1]);
#pragma unroll
                for (int j = 0; j < 6; j++) po[j] = pack2(v[2*j+1], v[2*j+2]);
                const unsigned long long* wr = wdd0 + ci*49 + dy*7;  // +o*98+dx
#pragma unroll
                for (int dx = 0; dx < 7; dx++) {
#pragma unroll
                    for (int o = 0; o < 4; o++) {
                        unsigned long long wp = wr[o*98 + dx];  // broadcast
#pragma unroll
                        for (int k = 0; k < 4; k++) {
                            unsigned long long inp =
                                (dx & 1) ? po[(dx >> 1) + k] : pe[(dx >> 1) + k];
                            acc[o][k] = fma2(inp, wp, acc[o][k]);
                        }
                    }
                }
            }
        }
#pragma unroll
        for (int o = 0; o < 4; o++) {
            float res[8];
#pragma unroll
            for (int k = 0; k < 4; k++) unpack2(acc[o][k], res[2*k], res[2*k+1]);
            float4* dst = (float4*)(out + o*4096 + h*64 + ws);
            dst[0] = make_float4(res[0], res[1], res[2], res[3]);
            dst[1] = make_float4(res[4], res[5], res[6], res[7]);
        }
    }
}

// ---------------------------------------------------------------------------
// K1b: spike scan layer 1 — pure per-thread recurrence, no barriers.
// 16384 threads, thread owns 4 adjacent w-locations (float4 in, uchar4 out),
// depth-4 temporal prefetch.
// ---------------------------------------------------------------------------
__global__ void __launch_bounds__(64) k1b_scan1() {
    const int g = blockIdx.x*64 + threadIdx.x;      // 0..16383
    const int n = g >> 12, r = g & 4095;            // r: (c,h,wq) 4*64*16
    const float4* ub = (const float4*)g_u1 + (size_t)(n*TT)*4096 + r;  // +t*4096
    uchar4* sp = (uchar4*)g_s1 + (size_t)(n*TT)*4096 + r;              // +t*4096

    float m0 = 0.f, m1 = 0.f, m2 = 0.f, m3 = 0.f;
    float4 buf[4];
#pragma unroll
    for (int i = 0; i < 4; i++) buf[i] = ub[(size_t)i*4096];

#pragma unroll 1
    for (int tg = 0; tg < 25; tg++) {
        float4 c0 = buf[0], c1 = buf[1], c2 = buf[2], c3 = buf[3];
        if (tg < 24) {
#pragma unroll
            for (int i = 0; i < 4; i++)
                buf[i] = ub[(size_t)(tg*4 + 4 + i)*4096];
        }
#pragma unroll
        for (int i = 0; i < 4; i++) {
            float4 c = (i == 0) ? c0 : (i == 1) ? c1 : (i == 2) ? c2 : c3;
            m0 += c.x; float s0 = (m0 >= 1.f) ? 1.f : 0.f; m0 -= s0;
            m1 += c.y; float s1 = (m1 >= 1.f) ? 1.f : 0.f; m1 -= s1;
            m2 += c.z; float s2 = (m2 >= 1.f) ? 1.f : 0.f; m2 -= s2;
            m3 += c.w; float s3 = (m3 >= 1.f) ? 1.f : 0.f; m3 -= s3;
            sp[(size_t)(tg*4 + i)*4096] =
                make_uchar4((unsigned char)s0, (unsigned char)s1,
                            (unsigned char)s2, (unsigned char)s3);
        }
    }
}

// ---------------------------------------------------------------------------
// K2a: dp4a 4x4 pool of s1 bytes + conv2 4->8ch 7x7 pad3 on 16x16.
// One slab per block (grid 400), 128 threads: thread = (ocHalf, h, w-quad)
// = 4 output pixels x 4 oc as two f32x2 pixel-pairs per oc. Weight dup-packs
// in smem (broadcast LDS.64), each feeding 2 fma2; inputs via 3 LDS.128.
// ---------------------------------------------------------------------------
__global__ void __launch_bounds__(128) k2a_conv2() {
    const int b = blockIdx.x;                   // n*100 + t
    __shared__ float pp[4*22*24];               // padded pooled input
    __shared__ unsigned long long wdd[1568];    // (w,w) dup packs of c_w1

    const int tid = threadIdx.x;
    for (int i = tid; i < 1568; i += 128) {
        float wv = c_w1[i];                     // i = o*196 + ci*49 + dy*7 + dx
        wdd[i] = pack2(wv, wv);
    }
    for (int i = tid; i < 2112; i += 128) pp[i] = 0.f;
    __syncthreads();

    // pool: 1024 pooled values, dp4a over 4 rows of 4 spike bytes
    const unsigned char* sslab = g_s1 + (size_t)b * 16384;
    for (int i = tid; i < 1024; i += 128) {
        int ci = i >> 8, ph = (i >> 4) & 15, pw = i & 15;
        const unsigned int* srow =
            (const unsigned int*)(sslab + ci*4096 + ph*256) + pw;
        int s = 0;
#pragma unroll
        for (int rr = 0; rr < 4; rr++) s = dp4a_sum(srow[rr*16], s);
        pp[ci*528 + (ph+3)*24 + (pw+3)] = (float)s * 0.0625f;
    }
    __syncthreads();

    const int oh = tid >> 6;                 // oc half: oc = oh*4 + o
    const int l = tid & 63;
    const int h = l >> 2, w0 = (l & 3) << 2; // 4-pixel group
    unsigned long long acc[4][2];
#pragma unroll
    for (int o = 0; o < 4; o++) { acc[o][0] = 0ull; acc[o][1] = 0ull; }

#pragma unroll 1
    for (int ci = 0; ci < 4; ci++) {
#pragma unroll 1
        for (int dy = 0; dy < 7; dy++) {
            const float* row = pp + ci*528 + (h+dy)*24 + w0;  // 16B-aligned
            float v[12];
#pragma unroll
            for (int q = 0; q < 3; q++) {
                float4 t4 = ((const float4*)row)[q];
                v[4*q+0] = t4.x; v[4*q+1] = t4.y;
                v[4*q+2] = t4.z; v[4*q+3] = t4.w;
            }
            unsigned long long pk[9];
#pragma unroll
            for (int j = 0; j < 9; j++) pk[j] = pack2(v[j], v[j+1]);
            const unsigned long long* wr = wdd + (oh*4)*196 + ci*49 + dy*7;
#pragma unroll
            for (int dx = 0; dx < 7; dx++) {
#pragma unroll
                for (int o = 0; o < 4; o++) {
                    unsigned long long wp = wr[o*196 + dx];   // broadcast
                    acc[o][0] = fma2(pk[dx],     wp, acc[o][0]);
                    acc[o][1] = fma2(pk[dx + 2], wp, acc[o][1]);
                }
            }
        }
    }
    float* out = g_u2 + (size_t)b * 2048 + oh*1024;
#pragma unroll
    for (int o = 0; o < 4; o++) {
        float r0, r1, r2, r3;
        unpack2(acc[o][0], r0, r1);
        unpack2(acc[o][1], r2, r3);
        *(float4*)(out + o*256 + h*16 + w0) = make_float4(r0, r1, r2, r3);
    }
}

// ---------------------------------------------------------------------------
// K2b: spike scan layer 2 -> s2 bytes. 8192 threads, depth-4 prefetch.
// ---------------------------------------------------------------------------
__global__ void __launch_bounds__(32) k2b_scan2() {
    const int g = blockIdx.x*32 + threadIdx.x;      // 0..8191
    const int n = g >> 11, r = g & 2047;
    const float* ub = g_u2 + (size_t)(n*TT)*2048 + r;     // +t*2048
    unsigned char* sp = g_s2 + (size_t)(n*TT)*2048 + r;

    float m = 0.f;
    float buf[4];
#pragma unroll
    for (int i = 0; i < 4; i++) buf[i] = ub[(size_t)i*2048];

#pragma unroll 1
    for (int tg = 0; tg < 25; tg++) {
        float c0 = buf[0], c1 = buf[1], c2 = buf[2], c3 = buf[3];
        if (tg < 24) {
#pragma unroll
            for (int i = 0; i < 4; i++)
                buf[i] = ub[(size_t)(tg*4 + 4 + i)*2048];
        }
        float cc[4] = {c0, c1, c2, c3};
#pragma unroll
        for (int i = 0; i < 4; i++) {
            m += cc[i];
            float s = (m >= 1.f) ? 1.f : 0.f;
            m -= s;
            sp[(size_t)(tg*4 + i)*2048] = (unsigned char)s;
        }
    }
}

// ---------------------------------------------------------------------------
// K3: dp4a pool of s2 + einsum with wl -> out (n,2,t). 400 blocks x 64 thr.
// ---------------------------------------------------------------------------
__global__ void __launch_bounds__(64) k3_out(float* __restrict__ out) {
    const int b = blockIdx.x;
    const int n = b / 100, t = b - n*100;
    const unsigned int* slab = (const unsigned int*)(g_s2 + (size_t)b * 2048);
    const int tid = threadIdx.x;
    float a0 = 0.f, a1 = 0.f;
    for (int i = tid; i < 512; i += 64) {
        int cnt = dp4a_sum(slab[i], 0);
        int cc = i >> 6;
        int hh = (i >> 2) & 15;
        int wq = i & 3;
        int wi = cc*16 + (hh >> 2)*4 + wq;
        float f = (float)cnt;
        a0 += f * c_wl[wi];
        a1 += f * c_wl[128 + wi];
    }
    __shared__ float r0[64], r1[64];
    r0[tid] = a0; r1[tid] = a1;
    __syncthreads();
    if (tid < 32) {
        float v0 = r0[tid] + r0[tid+32];
        float v1 = r1[tid] + r1[tid+32];
#pragma unroll
        for (int off = 16; off > 0; off >>= 1) {
            v0 += __shfl_down_sync(0xffffffffu, v0, off);
            v1 += __shfl_down_sync(0xffffffffu, v1, off);
        }
        if (tid == 0) {
            out[(n*2 + 0)*100 + t] = v0 * 0.0625f;
            out[(n*2 + 1)*100 + t] = v1 * 0.0625f;
        }
    }
}

// ---------------------------------------------------------------------------
extern "C" void kernel_launch(void* const* d_in, const int* in_sizes, int n_in,
                              void* d_out, int out_size) {
    (void)in_sizes; (void)n_in; (void)out_size;
    const float* data = (const float*)d_in[0];

    cudaMemcpyToSymbolAsync(c_w0, d_in[1], sizeof(float)*392,  0,
                            cudaMemcpyDeviceToDevice, 0);
    cudaMemcpyToSymbolAsync(c_w1, d_in[2], sizeof(float)*1568, 0,
                            cudaMemcpyDeviceToDevice, 0);
    cudaMemcpyToSymbolAsync(c_wl, d_in[3], sizeof(float)*256,  0,
                            cudaMemcpyDeviceToDevice, 0);

    k0_pool  <<<512, 256>>>(data);
    k1a_conv1<<<400, 256>>>();
    k1b_scan1<<<256,  64>>>();
    k2a_conv2<<<400, 128>>>();
    k2b_scan2<<<256,  32>>>();
    k3_out   <<<400,  64>>>((float*)d_out);
}

// round 5
// speedup vs baseline: 1.1044x; 1.0885x over previous
#include <cuda_runtime.h>
#include <cstdint>

// ---------------------------------------------------------------------------
// SLAYER SNN pipeline, t-major intermediates:
//   K0 : pool4 input (n,c,256,256,t) -> p0 (n,t,2,64,64)     [DRAM-bound floor]
//   K1a: conv1 7x7 pad3 (2->4) per (n,t) slab -> u1          [f32x2 oc-pairs]
//   K1b: spike scan over t + fused 4x4 pool via shfl -> p1   [no s1 buffer]
//   K2a: conv2 (4->8) per slab, 256 thr, 2px x 4oc -> u2     [f32x2 oc-pairs]
//   K2b: spike scan over t -> s2 bytes
//   K3 : dp4a pool + einsum wl -> out (n,2,t)
// ---------------------------------------------------------------------------

#define NB 4
#define TT 100

__device__ float g_p0[NB*TT*2*64*64];          // 3,276,800 floats
__device__ float g_u1[NB*TT*4*64*64];          // 6,553,600 floats
__device__ float g_p1[NB*TT*4*16*16];          //   409,600 floats
__device__ float g_u2[NB*TT*8*16*16];          //   819,200 floats
__device__ unsigned char g_s2[NB*TT*8*16*16];  //   819,200 bytes

__constant__ float c_w0[4*2*7*7];    // 392
__constant__ float c_w1[8*4*7*7];    // 1568
__constant__ float c_wl[2*8*4*4];    // 256

// ---- packed f32x2 helpers (sm_100+) ----
__device__ __forceinline__ unsigned long long pack2(float lo, float hi) {
    unsigned long long r;
    asm("mov.b64 %0, {%1, %2};" : "=l"(r) : "f"(lo), "f"(hi));
    return r;
}
__device__ __forceinline__ void unpack2(unsigned long long v, float& lo, float& hi) {
    asm("mov.b64 {%0, %1}, %2;" : "=f"(lo), "=f"(hi) : "l"(v));
}
__device__ __forceinline__ unsigned long long fma2(unsigned long long a,
                                                   unsigned long long b,
                                                   unsigned long long c) {
    unsigned long long d;
    asm("fma.rn.f32x2 %0, %1, %2, %3;" : "=l"(d) : "l"(a), "l"(b), "l"(c));
    return d;
}
__device__ __forceinline__ int dp4a_sum(unsigned int u, int acc) {
    int r;
    asm("dp4a.u32.u32 %0, %1, %2, %3;" : "=r"(r)
        : "r"(u), "r"(0x01010101u), "r"(acc));
    return r;
}

// ---------------------------------------------------------------------------
// K0: 4x4 average pool of raw input with layout transpose to t-major.
// 512 blocks = (n,c,H64), 256 threads. Reads 210MB coalesced (float4 over t).
// ---------------------------------------------------------------------------
__global__ void __launch_bounds__(256) k0_pool(const float* __restrict__ in) {
    const int b = blockIdx.x;
    const int n = b >> 7, c = (b >> 6) & 1, H = b & 63;
    __shared__ float sm[TT][65];   // [t][W]

    const float* base = in + (size_t)((n*2 + c)*256 + H*4) * 25600;

    for (int idx = threadIdx.x; idx < 1600; idx += 256) {
        int W  = idx / 25;
        int tq = idx - W*25;           // t-quad 0..24
        const float4* p = (const float4*)(base + (size_t)(W*4)*100 + tq*4);
        float4 s = make_float4(0.f, 0.f, 0.f, 0.f);
#pragma unroll
        for (int dy = 0; dy < 4; dy++)
#pragma unroll
            for (int dx = 0; dx < 4; dx++) {
                float4 v = p[dy*6400 + dx*25];
                s.x += v.x; s.y += v.y; s.z += v.z; s.w += v.w;
            }
        int t = tq*4;
        sm[t+0][W] = s.x*0.0625f; sm[t+1][W] = s.y*0.0625f;
        sm[t+2][W] = s.z*0.0625f; sm[t+3][W] = s.w*0.0625f;
    }
    __syncthreads();
    const size_t ob = ((size_t)(n*TT)*2 + c)*4096 + H*64;
    for (int idx = threadIdx.x; idx < 6400; idx += 256) {
        int t = idx >> 6, W = idx & 63;
        g_p0[ob + (size_t)t*8192 + W] = sm[t][W];
    }
}

// ---------------------------------------------------------------------------
// K1a: conv1 2->4ch 7x7 pad3 on 64x64, one (n,t) slab per block, 256 threads.
// Thread = 8 px x 4 oc: f32x2 lanes = oc-pair, weights pre-packed
// (w[2o], w[2o+1]) in smem; input dup-packed once per (ci,dy) row.
// Per (ci,dy): 4 LDS.128 + 14 dup + 14 LDS.64 + 112 fma2  (~1.15x floor).
// ---------------------------------------------------------------------------
__global__ void __launch_bounds__(256, 2) k1a_conv1() {
    const int b = blockIdx.x;              // n*100 + t
    __shared__ float si[2*70*72];          // zero-padded input, stride 72
    __shared__ unsigned long long wp0[196];  // [op2][ci2][dy7][dx7] oc pairs

    for (int i = threadIdx.x; i < 196; i += 256) {
        int op = i / 98, q = i - op*98;
        wp0[i] = pack2(c_w0[(2*op)*98 + q], c_w0[(2*op+1)*98 + q]);
    }
    for (int i = threadIdx.x; i < 2*70*72; i += 256) si[i] = 0.f;
    __syncthreads();
    const float* slab = g_p0 + (size_t)b * 8192;
    for (int i = threadIdx.x; i < 8192; i += 256) {
        int ci = i >> 12, h = (i >> 6) & 63, w = i & 63;
        si[ci*5040 + (h+3)*72 + (w+3)] = slab[i];
    }
    __syncthreads();

    float* out = g_u1 + (size_t)b * 16384;

#pragma unroll 1
    for (int rep = 0; rep < 2; rep++) {
        const int pos = threadIdx.x + (rep << 8);   // 0..511
        const int h  = pos >> 3;
        const int ws = (pos & 7) << 3;              // 8-pixel segment start
        unsigned long long acc[2][8];
#pragma unroll
        for (int op = 0; op < 2; op++)
#pragma unroll
            for (int px = 0; px < 8; px++) acc[op][px] = 0ull;

#pragma unroll 1
        for (int ci = 0; ci < 2; ci++) {
#pragma unroll 1
            for (int dy = 0; dy < 7; dy++) {
                const float* r = si + ci*5040 + (h+dy)*72 + ws;  // 16B-aligned
                float v[16];
#pragma unroll
                for (int q = 0; q < 4; q++) {
                    float4 t4 = ((const float4*)r)[q];
                    v[4*q+0] = t4.x; v[4*q+1] = t4.y;
                    v[4*q+2] = t4.z; v[4*q+3] = t4.w;
                }
                unsigned long long pd[14];
#pragma unroll
                for (int j = 0; j < 14; j++) pd[j] = pack2(v[j], v[j]);
                const unsigned long long* wr = wp0 + ci*49 + dy*7;  // +op*98+dx
#pragma unroll
                for (int dx = 0; dx < 7; dx++) {
                    unsigned long long wa = wr[dx];        // oc pair (0,1)
                    unsigned long long wb = wr[98 + dx];   // oc pair (2,3)
#pragma unroll
                    for (int px = 0; px < 8; px++) {
                        acc[0][px] = fma2(pd[px+dx], wa, acc[0][px]);
                        acc[1][px] = fma2(pd[px+dx], wb, acc[1][px]);
                    }
                }
            }
        }
#pragma unroll
        for (int op = 0; op < 2; op++) {
            float lo[8], hi[8];
#pragma unroll
            for (int px = 0; px < 8; px++) unpack2(acc[op][px], lo[px], hi[px]);
            float4* d0 = (float4*)(out + (2*op  )*4096 + h*64 + ws);
            float4* d1 = (float4*)(out + (2*op+1)*4096 + h*64 + ws);
            d0[0] = make_float4(lo[0], lo[1], lo[2], lo[3]);
            d0[1] = make_float4(lo[4], lo[5], lo[6], lo[7]);
            d1[0] = make_float4(hi[0], hi[1], hi[2], hi[3]);
            d1[1] = make_float4(hi[4], hi[5], hi[6], hi[7]);
        }
    }
}

// ---------------------------------------------------------------------------
// K1b: spike scan layer 1 + fused 4x4 pool -> p1 (no s1 buffer at all).
// Thread = (n,c,ph,pw,hi): float4 of w at row ph*4+hi. Pool = per-thread sum
// of 4 spikes + 2 shfl_xor over the 4 hi lanes; lane hi==0 stores pooled val.
// Spikes batched 4 t per group so the shfl chains overlap.
// ---------------------------------------------------------------------------
__global__ void __launch_bounds__(64) k1b_scan1() {
    const int g = blockIdx.x*64 + threadIdx.x;      // 0..16383
    const int hi = g & 3, pw = (g >> 2) & 15, ph = (g >> 6) & 15;
    const int c = (g >> 10) & 3, n = g >> 12;

    const float4* ub = (const float4*)g_u1
        + ((size_t)(n*TT)*4 + c)*1024 + (ph*4 + hi)*16 + pw;   // +t*4096
    float* pb = g_p1 + ((size_t)(n*TT)*4 + c)*256 + ph*16 + pw; // +t*1024

    float m0 = 0.f, m1 = 0.f, m2 = 0.f, m3 = 0.f;
    float4 buf[4];
#pragma unroll
    for (int i = 0; i < 4; i++) buf[i] = ub[(size_t)i*4096];

#pragma unroll 1
    for (int tg = 0; tg < 25; tg++) {
        float4 c0 = buf[0], c1 = buf[1], c2 = buf[2], c3 = buf[3];
        if (tg < 24) {
#pragma unroll
            for (int i = 0; i < 4; i++)
                buf[i] = ub[(size_t)(tg*4 + 4 + i)*4096];
        }
        float ps[4];
        float4 cc[4] = {c0, c1, c2, c3};
#pragma unroll
        for (int i = 0; i < 4; i++) {
            float4 u = cc[i];
            m0 += u.x; float s0 = (m0 >= 1.f) ? 1.f : 0.f; m0 -= s0;
            m1 += u.y; float s1 = (m1 >= 1.f) ? 1.f : 0.f; m1 -= s1;
            m2 += u.z; float s2 = (m2 >= 1.f) ? 1.f : 0.f; m2 -= s2;
            m3 += u.w; float s3 = (m3 >= 1.f) ? 1.f : 0.f; m3 -= s3;
            ps[i] = (s0 + s1) + (s2 + s3);
        }
#pragma unroll
        for (int i = 0; i < 4; i++)
            ps[i] += __shfl_xor_sync(0xffffffffu, ps[i], 1);
#pragma unroll
        for (int i = 0; i < 4; i++)
            ps[i] += __shfl_xor_sync(0xffffffffu, ps[i], 2);
        if (hi == 0) {
#pragma unroll
            for (int i = 0; i < 4; i++)
                pb[(size_t)(tg*4 + i)*1024] = ps[i] * 0.0625f;
        }
    }
}

// ---------------------------------------------------------------------------
// K2a: conv2 4->8ch 7x7 pad3 on 16x16 from pooled p1.
// One slab per block, 256 threads: thread = (ocGroup, h, w-pair) = 2 px x 4 oc
// as f32x2 oc-pairs (weights naturally paired in smem). Per (ci,dy):
// 4 LDS.64 + 8 dup + 14 LDS.64 + 28 fma2.
// ---------------------------------------------------------------------------
__global__ void __launch_bounds__(256) k2a_conv2() {
    const int b = blockIdx.x;                   // n*100 + t
    __shared__ float pp[4*22*24];               // padded pooled input (2112)
    __shared__ unsigned long long wq1[784];     // [op4][ci4][dy7][dx7] oc pairs

    const int tid = threadIdx.x;
    for (int i = tid; i < 784; i += 256) {
        int op = i / 196, q = i - op*196;
        wq1[i] = pack2(c_w1[(2*op)*196 + q], c_w1[(2*op+1)*196 + q]);
    }
    for (int i = tid; i < 2112; i += 256) pp[i] = 0.f;
    __syncthreads();
    const float* slab = g_p1 + (size_t)b * 1024;
    for (int i = tid; i < 1024; i += 256) {
        int ci = i >> 8, ph = (i >> 4) & 15, pw = i & 15;
        pp[ci*528 + (ph+3)*24 + (pw+3)] = slab[i];
    }
    __syncthreads();

    const int ocg = tid >> 7;                // 0: oc0-3, 1: oc4-7
    const int l = tid & 127;
    const int h = l >> 3, w0 = (l & 7) << 1; // 2-pixel pair
    unsigned long long acc[2][2];            // [op][px]
    acc[0][0] = acc[0][1] = acc[1][0] = acc[1][1] = 0ull;

#pragma unroll 1
    for (int ci = 0; ci < 4; ci++) {
#pragma unroll 1
        for (int dy = 0; dy < 7; dy++) {
            const float* row = pp + ci*528 + (h+dy)*24 + w0;  // 8B-aligned
            float v[8];
#pragma unroll
            for (int q = 0; q < 4; q++) {
                float2 t2 = ((const float2*)row)[q];
                v[2*q]   = t2.x;
                v[2*q+1] = t2.y;
            }
            unsigned long long pd[8];
#pragma unroll
            for (int j = 0; j < 8; j++) pd[j] = pack2(v[j], v[j]);
            const unsigned long long* wr = wq1 + (ocg*2)*196 + ci*49 + dy*7;
#pragma unroll
            for (int dx = 0; dx < 7; dx++) {
                unsigned long long wa = wr[dx];
                unsigned long long wb = wr[196 + dx];
                acc[0][0] = fma2(pd[dx],   wa, acc[0][0]);
                acc[0][1] = fma2(pd[dx+1], wa, acc[0][1]);
                acc[1][0] = fma2(pd[dx],   wb, acc[1][0]);
                acc[1][1] = fma2(pd[dx+1], wb, acc[1][1]);
            }
        }
    }
    float* out = g_u2 + (size_t)b * 2048 + (ocg*4)*256 + h*16 + w0;
#pragma unroll
    for (int op = 0; op < 2; op++)
#pragma unroll
        for (int px = 0; px < 2; px++) {
            float r0, r1;
            unpack2(acc[op][px], r0, r1);
            out[(2*op  )*256 + px] = r0;
            out[(2*op+1)*256 + px] = r1;
        }
}

// ---------------------------------------------------------------------------
// K2b: spike scan layer 2 -> s2 bytes. 8192 threads, depth-4 prefetch.
// ---------------------------------------------------------------------------
__global__ void __launch_bounds__(32) k2b_scan2() {
    const int g = blockIdx.x*32 + threadIdx.x;      // 0..8191
    const int n = g >> 11, r = g & 2047;
    const float* ub = g_u2 + (size_t)(n*TT)*2048 + r;     // +t*2048
    unsigned char* sp = g_s2 + (size_t)(n*TT)*2048 + r;

    float m = 0.f;
    float buf[4];
#pragma unroll
    for (int i = 0; i < 4; i++) buf[i] = ub[(size_t)i*2048];

#pragma unroll 1
    for (int tg = 0; tg < 25; tg++) {
        float c0 = buf[0], c1 = buf[1], c2 = buf[2], c3 = buf[3];
        if (tg < 24) {
#pragma unroll
            for (int i = 0; i < 4; i++)
                buf[i] = ub[(size_t)(tg*4 + 4 + i)*2048];
        }
        float cc[4] = {c0, c1, c2, c3};
#pragma unroll
        for (int i = 0; i < 4; i++) {
            m += cc[i];
            float s = (m >= 1.f) ? 1.f : 0.f;
            m -= s;
            sp[(size_t)(tg*4 + i)*2048] = (unsigned char)s;
        }
    }
}

// ---------------------------------------------------------------------------
// K3: dp4a pool of s2 + einsum with wl -> out (n,2,t). 400 blocks x 64 thr.
// ---------------------------------------------------------------------------
__global__ void __launch_bounds__(64) k3_out(float* __restrict__ out) {
    const int b = blockIdx.x;
    const int n = b / 100, t = b - n*100;
    const unsigned int* slab = (const unsigned int*)(g_s2 + (size_t)b * 2048);
    const int tid = threadIdx.x;
    float a0 = 0.f, a1 = 0.f;
    for (int i = tid; i < 512; i += 64) {
        int cnt = dp4a_sum(slab[i], 0);
        int cc = i >> 6;
        int hh = (i >> 2) & 15;
        int wq = i & 3;
        int wi = cc*16 + (hh >> 2)*4 + wq;
        float f = (float)cnt;
        a0 += f * c_wl[wi];
        a1 += f * c_wl[128 + wi];
    }
    __shared__ float r0[64], r1[64];
    r0[tid] = a0; r1[tid] = a1;
    __syncthreads();
    if (tid < 32) {
        float v0 = r0[tid] + r0[tid+32];
        float v1 = r1[tid] + r1[tid+32];
#pragma unroll
        for (int off = 16; off > 0; off >>= 1) {
            v0 += __shfl_down_sync(0xffffffffu, v0, off);
            v1 += __shfl_down_sync(0xffffffffu, v1, off);
        }
        if (tid == 0) {
            out[(n*2 + 0)*100 + t] = v0 * 0.0625f;
            out[(n*2 + 1)*100 + t] = v1 * 0.0625f;
        }
    }
}

// ---------------------------------------------------------------------------
extern "C" void kernel_launch(void* const* d_in, const int* in_sizes, int n_in,
                              void* d_out, int out_size) {
    (void)in_sizes; (void)n_in; (void)out_size;
    const float* data = (const float*)d_in[0];

    cudaMemcpyToSymbolAsync(c_w0, d_in[1], sizeof(float)*392,  0,
                            cudaMemcpyDeviceToDevice, 0);
    cudaMemcpyToSymbolAsync(c_w1, d_in[2], sizeof(float)*1568, 0,
                            cudaMemcpyDeviceToDevice, 0);
    cudaMemcpyToSymbolAsync(c_wl, d_in[3], sizeof(float)*256,  0,
                            cudaMemcpyDeviceToDevice, 0);

    k0_pool  <<<512, 256>>>(data);
    k1a_conv1<<<400, 256>>>();
    k1b_scan1<<<256,  64>>>();
    k2a_conv2<<<400, 256>>>();
    k2b_scan2<<<256,  32>>>();
    k3_out   <<<400,  64>>>((float*)d_out);
}